// round 7
// baseline (speedup 1.0000x reference)
#include <cuda_runtime.h>
#include <math.h>
#include <stdint.h>

#define NB 8
#define NS 1024
#define NE 1024
#define NH 16
#define ND 64
#define NM (NB*NS)

// ---------------- device-global scratch (allocation-free) ------------------
__device__ float g_qh[NB*NH*NS*ND];
__device__ float g_kh[NB*NH*NS*ND];
__device__ float g_vh[NB*NH*NS*ND];
__device__ float g_ctx[NB*NS*NE];
__device__ float g_qr[NM*NE];       // tf32-rounded inputs
__device__ float g_kr[NM*NE];
__device__ float g_vr[NM*NE];
__device__ float g_wqT[NH*ND*NE];   // [n=h*64+e][k], tf32-rounded
__device__ float g_wkT[NH*ND*NE];
__device__ float g_wvT[NH*ND*NE];
__device__ float g_woT[NE*NE];

__device__ __forceinline__ float tf32rna(float x) {
    uint32_t u;
    asm("cvt.rna.tf32.f32 %0, %1;" : "=r"(u) : "f"(x));
    return __uint_as_float(u);
}
__device__ __forceinline__ uint32_t smem_u32(const void* p) {
    uint32_t a;
    asm("{ .reg .u64 t; cvta.to.shared.u64 t, %1; cvt.u32.u64 %0, t; }" : "=r"(a) : "l"(p));
    return a;
}
__device__ __forceinline__ void cpa16(uint32_t dst, const void* src) {
    asm volatile("cp.async.cg.shared.global [%0], [%1], 16;" :: "r"(dst), "l"(src));
}
__device__ __forceinline__ void cpa_commit() {
    asm volatile("cp.async.commit_group;" ::: "memory");
}
template<int N> __device__ __forceinline__ void cpa_wait() {
    asm volatile("cp.async.wait_group %0;" :: "n"(N) : "memory");
}
__device__ __forceinline__ void mma16n8k8(float* d, const uint32_t* a, uint32_t b0, uint32_t b1) {
    asm volatile(
        "mma.sync.aligned.m16n8k8.row.col.f32.tf32.tf32.f32 "
        "{%0,%1,%2,%3}, {%4,%5,%6,%7}, {%8,%9}, {%0,%1,%2,%3};"
        : "+f"(d[0]), "+f"(d[1]), "+f"(d[2]), "+f"(d[3])
        : "r"(a[0]), "r"(a[1]), "r"(a[2]), "r"(a[3]), "r"(b0), "r"(b1));
}

// ---------------- GEMM: 128x256 tile, 8 warps of 64x64, 3-stage cp.async ---
#define TSTRIDE 36
#define ATILEF (128*TSTRIDE)             // 4608 floats
#define BTILEF (256*TSTRIDE)             // 9216 floats
#define STAGEF (ATILEF+BTILEF)           // 13824 floats = 55296 B
#define GSTAGES 3
#define GSMEM_BYTES (GSTAGES*STAGEF*4)   // 165888

__device__ __forceinline__ void gemm_body(
    const float* __restrict__ A, const float* __restrict__ BT,
    const float* __restrict__ bias, float* __restrict__ ob, int osel,
    float* sm)
{
    const uint32_t su = smem_u32(sm);
    const int tid  = threadIdx.x;
    const int wid  = tid >> 5;
    const int lane = tid & 31;
    const int g    = lane >> 2;
    const int t    = lane & 3;
    const int m0 = blockIdx.x * 128;
    const int n0 = blockIdx.y * 256;
    const int warp_m = (wid & 1) * 64;
    const int warp_n = (wid >> 1) * 64;

    const int lrow = tid >> 3;        // 0..31
    const int lc4  = tid & 7;         // 0..7

    auto issue = [&](int c, int s) {
        const int k0 = c * 32;
        const uint32_t base = su + s * (STAGEF * 4);
#pragma unroll
        for (int i = 0; i < 4; i++) {
            int row = lrow + i * 32;
            cpa16(base + (row * TSTRIDE + lc4 * 4) * 4,
                  A + (size_t)(m0 + row) * NE + k0 + lc4 * 4);
        }
#pragma unroll
        for (int i = 0; i < 8; i++) {
            int row = lrow + i * 32;
            cpa16(base + ATILEF * 4 + (row * TSTRIDE + lc4 * 4) * 4,
                  BT + (size_t)(n0 + row) * NE + k0 + lc4 * 4);
        }
    };

    issue(0, 0); cpa_commit();
    issue(1, 1); cpa_commit();

    float d[4][8][4];
#pragma unroll
    for (int mi = 0; mi < 4; mi++)
#pragma unroll
        for (int ni = 0; ni < 8; ni++)
#pragma unroll
            for (int j = 0; j < 4; j++) d[mi][ni][j] = 0.f;

    for (int c = 0; c < 32; c++) {
        if (c + 2 < 32) { issue(c + 2, (c + 2) % 3); cpa_commit(); }
        if (c < 30) cpa_wait<2>(); else if (c == 30) cpa_wait<1>(); else cpa_wait<0>();
        __syncthreads();

        const int st = c % 3;
        const float* As = sm + st * STAGEF + (warp_m + g) * TSTRIDE;
        const float* Bs = sm + st * STAGEF + ATILEF + (warp_n + g) * TSTRIDE;
#pragma unroll
        for (int ks = 0; ks < 4; ks++) {
            const int k0 = ks * 8 + t;
            uint32_t a[4][4];
#pragma unroll
            for (int mi = 0; mi < 4; mi++) {
                const float* ap = As + mi * 16 * TSTRIDE + k0;
                a[mi][0] = __float_as_uint(ap[0]);
                a[mi][1] = __float_as_uint(ap[8 * TSTRIDE]);
                a[mi][2] = __float_as_uint(ap[4]);
                a[mi][3] = __float_as_uint(ap[8 * TSTRIDE + 4]);
            }
#pragma unroll
            for (int ni = 0; ni < 8; ni++) {
                const float* bp = Bs + ni * 8 * TSTRIDE + k0;
                uint32_t b0 = __float_as_uint(bp[0]);
                uint32_t b1 = __float_as_uint(bp[4]);
#pragma unroll
                for (int mi = 0; mi < 4; mi++)
                    mma16n8k8(d[mi][ni], a[mi], b0, b1);
            }
        }
        __syncthreads();
    }

    // epilogue: bias + store (proj outputs rounded to tf32 for downstream mma)
#pragma unroll
    for (int mi = 0; mi < 4; mi++) {
#pragma unroll
        for (int ni = 0; ni < 8; ni++) {
            const int r0  = m0 + warp_m + mi * 16 + g;
            const int r1  = r0 + 8;
            const int col = n0 + warp_n + ni * 8 + t * 2;
            const float bx = bias[col], by = bias[col + 1];
            float2 v0, v1;
            v0.x = d[mi][ni][0] + bx; v0.y = d[mi][ni][1] + by;
            v1.x = d[mi][ni][2] + bx; v1.y = d[mi][ni][3] + by;
            if (osel < 3) {
                v0.x = tf32rna(v0.x); v0.y = tf32rna(v0.y);
                v1.x = tf32rna(v1.x); v1.y = tf32rna(v1.y);
                const int h = col >> 6, e = col & 63;
                float* d0 = ob + ((size_t)((r0 >> 10) * NH + h) * NS + (r0 & 1023)) * ND + e;
                float* d1 = ob + ((size_t)((r1 >> 10) * NH + h) * NS + (r1 & 1023)) * ND + e;
                *(float2*)d0 = v0;
                *(float2*)d1 = v1;
            } else {
                *(float2*)(ob + (size_t)r0 * NE + col) = v0;
                *(float2*)(ob + (size_t)r1 * NE + col) = v1;
            }
        }
    }
}

// fused Q/K/V projection GEMMs: blockIdx.z = 0/1/2
__global__ __launch_bounds__(256, 1) void proj_gemm(
    const float* __restrict__ bq, const float* __restrict__ bk,
    const float* __restrict__ bv)
{
    extern __shared__ float sm[];
    const int z = blockIdx.z;
    const float* A  = (z == 0) ? g_qr  : (z == 1) ? g_kr  : g_vr;
    const float* BT = (z == 0) ? g_wqT : (z == 1) ? g_wkT : g_wvT;
    const float* bias = (z == 0) ? bq : (z == 1) ? bk : bv;
    float* ob = (z == 0) ? g_qh : (z == 1) ? g_kh : g_vh;
    gemm_body(A, BT, bias, ob, z, sm);
}

__global__ __launch_bounds__(256, 1) void out_gemm(
    const float* __restrict__ bo, float* __restrict__ out)
{
    extern __shared__ float sm[];
    gemm_body(g_ctx, g_woT, bo, out, 3, sm);
}

// ---------------- attention: 4 warps x 32 q-rows, tf32 mma flash -----------
#define KSTR 68
#define VSTR 72
#define QPF  (128*KSTR)                 // 8704 floats (Q, reused as P)
#define KVF  (64*KSTR + 64*VSTR)        // 8960 floats per stage
#define ASTAGES 2
#define ASMEM_BYTES ((QPF + ASTAGES*KVF)*4)  // 106496 -> 2 CTAs/SM

__global__ __launch_bounds__(128, 2) void attn_mma()
{
    extern __shared__ float smf[];
    const uint32_t su = smem_u32(smf);
    const int tid = threadIdx.x, wid = tid >> 5, lane = tid & 31;
    const int g = lane >> 2, t = lane & 3;
    const int bh = blockIdx.y;
    const int s0 = blockIdx.x * 128;
    const int w32 = wid * 32;
    const float* Qp = g_qh + (size_t)bh * NS * ND;
    const float* Kp = g_kh + (size_t)bh * NS * ND;
    const float* Vp = g_vh + (size_t)bh * NS * ND;

    const int lkv = tid >> 4;          // 0..7
    const int lc4 = tid & 15;          // 0..15

    auto issue_kv = [&](int kt, int st) {
        const uint32_t kB = su + QPF * 4 + st * (KVF * 4);
        const uint32_t vB = kB + 64 * KSTR * 4;
        const float* Ks = Kp + (size_t)kt * 64 * ND;
        const float* Vs = Vp + (size_t)kt * 64 * ND;
#pragma unroll
        for (int i = 0; i < 8; i++) {
            int kv = lkv + i * 8;
            cpa16(kB + (kv * KSTR + lc4 * 4) * 4, Ks + (size_t)kv * ND + lc4 * 4);
            cpa16(vB + (kv * VSTR + lc4 * 4) * 4, Vs + (size_t)kv * ND + lc4 * 4);
        }
    };

    issue_kv(0, 0); cpa_commit();

    // Q tile -> smem (stride 68)
#pragma unroll
    for (int i = 0; i < 16; i++) {
        int idx = tid + i * 128;
        int row = idx >> 4, c4 = idx & 15;
        *(float4*)(smf + row * KSTR + c4 * 4) =
            *(const float4*)(Qp + (size_t)(s0 + row) * ND + c4 * 4);
    }
    __syncthreads();

    // persistent Q fragments (2 m-frags of 16 rows)
    uint32_t qf[8][2][4];
#pragma unroll
    for (int mf = 0; mf < 2; mf++) {
        const float* qp = smf + (w32 + mf * 16 + g) * KSTR;
#pragma unroll
        for (int ks = 0; ks < 8; ks++) {
            qf[ks][mf][0] = __float_as_uint(qp[ks * 8 + t]);
            qf[ks][mf][1] = __float_as_uint(qp[8 * KSTR + ks * 8 + t]);
            qf[ks][mf][2] = __float_as_uint(qp[ks * 8 + t + 4]);
            qf[ks][mf][3] = __float_as_uint(qp[8 * KSTR + ks * 8 + t + 4]);
        }
    }

    float o[2][8][4];
#pragma unroll
    for (int mf = 0; mf < 2; mf++)
#pragma unroll
        for (int ni = 0; ni < 8; ni++)
#pragma unroll
            for (int j = 0; j < 4; j++) o[mf][ni][j] = 0.f;
    float mS[2][2], lS[2][2];
#pragma unroll
    for (int mf = 0; mf < 2; mf++) {
        mS[mf][0] = -1e30f; mS[mf][1] = -1e30f;
        lS[mf][0] = 0.f;    lS[mf][1] = 0.f;
    }
    const float scale = 0.125f;

    for (int kt = 0; kt < 16; kt++) {
        if (kt + 1 < 16) { issue_kv(kt + 1, (kt + 1) & 1); cpa_commit(); }
        if (kt < 15) cpa_wait<1>(); else cpa_wait<0>();
        __syncthreads();

        const int st = kt & 1;
        const float* sK = smf + QPF + st * KVF;
        const float* sV = sK + 64 * KSTR;

        // S = Q @ K^T  (2 m-frags x 8 n-frags)
        float s[2][8][4];
#pragma unroll
        for (int mf = 0; mf < 2; mf++)
#pragma unroll
            for (int ni = 0; ni < 8; ni++)
#pragma unroll
                for (int j = 0; j < 4; j++) s[mf][ni][j] = 0.f;
#pragma unroll
        for (int ks = 0; ks < 8; ks++) {
            const float* kp = sK + ks * 8 + t;
#pragma unroll
            for (int ni = 0; ni < 8; ni++) {
                uint32_t b0 = __float_as_uint(kp[(ni * 8 + g) * KSTR]);
                uint32_t b1 = __float_as_uint(kp[(ni * 8 + g) * KSTR + 4]);
                mma16n8k8(s[0][ni], qf[ks][0], b0, b1);
                mma16n8k8(s[1][ni], qf[ks][1], b0, b1);
            }
        }

        // online softmax per m-frag (rows g and g+8)
#pragma unroll
        for (int mf = 0; mf < 2; mf++) {
            float mxA = -1e30f, mxB = -1e30f;
#pragma unroll
            for (int ni = 0; ni < 8; ni++) {
                mxA = fmaxf(mxA, fmaxf(s[mf][ni][0], s[mf][ni][1]));
                mxB = fmaxf(mxB, fmaxf(s[mf][ni][2], s[mf][ni][3]));
            }
            mxA = fmaxf(mxA, __shfl_xor_sync(0xffffffffu, mxA, 1));
            mxA = fmaxf(mxA, __shfl_xor_sync(0xffffffffu, mxA, 2));
            mxB = fmaxf(mxB, __shfl_xor_sync(0xffffffffu, mxB, 1));
            mxB = fmaxf(mxB, __shfl_xor_sync(0xffffffffu, mxB, 2));
            float mAn = fmaxf(mS[mf][0], mxA * scale);
            float mBn = fmaxf(mS[mf][1], mxB * scale);
            float aA = __expf(mS[mf][0] - mAn), aB = __expf(mS[mf][1] - mBn);
            float sumA = 0.f, sumB = 0.f;
#pragma unroll
            for (int ni = 0; ni < 8; ni++) {
                s[mf][ni][0] = __expf(s[mf][ni][0] * scale - mAn);
                s[mf][ni][1] = __expf(s[mf][ni][1] * scale - mAn);
                s[mf][ni][2] = __expf(s[mf][ni][2] * scale - mBn);
                s[mf][ni][3] = __expf(s[mf][ni][3] * scale - mBn);
                sumA += s[mf][ni][0] + s[mf][ni][1];
                sumB += s[mf][ni][2] + s[mf][ni][3];
            }
            sumA += __shfl_xor_sync(0xffffffffu, sumA, 1);
            sumA += __shfl_xor_sync(0xffffffffu, sumA, 2);
            sumB += __shfl_xor_sync(0xffffffffu, sumB, 1);
            sumB += __shfl_xor_sync(0xffffffffu, sumB, 2);
            lS[mf][0] = lS[mf][0] * aA + sumA;
            lS[mf][1] = lS[mf][1] * aB + sumB;
            mS[mf][0] = mAn; mS[mf][1] = mBn;
#pragma unroll
            for (int ni = 0; ni < 8; ni++) {
                o[mf][ni][0] *= aA; o[mf][ni][1] *= aA;
                o[mf][ni][2] *= aB; o[mf][ni][3] *= aB;
            }
        }

        // publish P (tf32-rounded) into QP buffer (own warp's 32 rows)
        __syncwarp();
#pragma unroll
        for (int mf = 0; mf < 2; mf++) {
            float* pr = smf + (w32 + mf * 16 + g) * KSTR;
#pragma unroll
            for (int ni = 0; ni < 8; ni++) {
                float2 v0; v0.x = tf32rna(s[mf][ni][0]); v0.y = tf32rna(s[mf][ni][1]);
                float2 v1; v1.x = tf32rna(s[mf][ni][2]); v1.y = tf32rna(s[mf][ni][3]);
                *(float2*)(pr + ni * 8 + 2 * t) = v0;
                *(float2*)(pr + 8 * KSTR + ni * 8 + 2 * t) = v1;
            }
        }
        __syncwarp();

        // O += P @ V
#pragma unroll
        for (int ks = 0; ks < 8; ks++) {
            uint32_t a[2][4];
#pragma unroll
            for (int mf = 0; mf < 2; mf++) {
                const float* pr = smf + (w32 + mf * 16 + g) * KSTR;
                a[mf][0] = __float_as_uint(pr[ks * 8 + t]);
                a[mf][1] = __float_as_uint(pr[8 * KSTR + ks * 8 + t]);
                a[mf][2] = __float_as_uint(pr[ks * 8 + t + 4]);
                a[mf][3] = __float_as_uint(pr[8 * KSTR + ks * 8 + t + 4]);
            }
            const float* vp = sV + (ks * 8 + t) * VSTR;
#pragma unroll
            for (int ni = 0; ni < 8; ni++) {
                uint32_t b0 = __float_as_uint(vp[ni * 8 + g]);
                uint32_t b1 = __float_as_uint(vp[4 * VSTR + ni * 8 + g]);
                mma16n8k8(o[0][ni], a[0], b0, b1);
                mma16n8k8(o[1][ni], a[1], b0, b1);
            }
        }
        __syncthreads();
    }

    // epilogue: normalize, round, write ctx
    const int b = bh >> 4, h = bh & 15;
#pragma unroll
    for (int mf = 0; mf < 2; mf++) {
        const float iA = 1.f / lS[mf][0], iB = 1.f / lS[mf][1];
        const int rA = s0 + w32 + mf * 16 + g, rB = rA + 8;
        float* dA = g_ctx + (size_t)(b * NS + rA) * NE + h * 64;
        float* dB = g_ctx + (size_t)(b * NS + rB) * NE + h * 64;
#pragma unroll
        for (int ni = 0; ni < 8; ni++) {
            float2 vA, vB2;
            vA.x  = tf32rna(o[mf][ni][0] * iA); vA.y  = tf32rna(o[mf][ni][1] * iA);
            vB2.x = tf32rna(o[mf][ni][2] * iB); vB2.y = tf32rna(o[mf][ni][3] * iB);
            *(float2*)(dA + ni * 8 + 2 * t) = vA;
            *(float2*)(dB + ni * 8 + 2 * t) = vB2;
        }
    }
}

// ---------------- small prep kernels ----------------------------------------
__global__ void round_kernel(const float* __restrict__ q, const float* __restrict__ k,
                             const float* __restrict__ v, int n4)
{
    const int z = blockIdx.z;
    const float* in = (z == 0) ? q : (z == 1) ? k : v;
    float* out = (z == 0) ? g_qr : (z == 1) ? g_kr : g_vr;
    int i = blockIdx.x * blockDim.x + threadIdx.x;
    for (; i < n4; i += gridDim.x * blockDim.x) {
        float4 w = ((const float4*)in)[i];
        w.x = tf32rna(w.x); w.y = tf32rna(w.y);
        w.z = tf32rna(w.z); w.w = tf32rna(w.w);
        ((float4*)out)[i] = w;
    }
}

__global__ void transpose_kernel(const float* __restrict__ in, int sel, int R, int C)
{
    __shared__ float tbuf[32][33];
    float* out = (sel == 0) ? g_wqT : (sel == 1) ? g_wkT : (sel == 2) ? g_wvT : g_woT;
    const float* I = in  + (size_t)blockIdx.z * R * C;
    float*       O = out + (size_t)blockIdx.z * R * C;
    int c0 = blockIdx.x * 32, r0 = blockIdx.y * 32;
#pragma unroll
    for (int j = threadIdx.y; j < 32; j += 8)
        tbuf[j][threadIdx.x] = I[(size_t)(r0 + j) * C + c0 + threadIdx.x];
    __syncthreads();
#pragma unroll
    for (int j = threadIdx.y; j < 32; j += 8)
        O[(size_t)(c0 + j) * R + r0 + threadIdx.x] = tf32rna(tbuf[threadIdx.x][j]);
}

// ---------------------------------------------------------------------------
extern "C" void kernel_launch(void* const* d_in, const int* in_sizes, int n_in,
                              void* d_out, int out_size)
{
    const float* q  = (const float*)d_in[0];
    const float* k  = (const float*)d_in[1];
    const float* v  = (const float*)d_in[2];
    const float* Wq = (const float*)d_in[3];
    const float* bq = (const float*)d_in[4];
    const float* Wk = (const float*)d_in[5];
    const float* bk = (const float*)d_in[6];
    const float* Wv = (const float*)d_in[7];
    const float* bv = (const float*)d_in[8];
    const float* Wo = (const float*)d_in[9];
    const float* bo = (const float*)d_in[10];
    float* out = (float*)d_out;

    cudaFuncSetAttribute(proj_gemm, cudaFuncAttributeMaxDynamicSharedMemorySize, GSMEM_BYTES);
    cudaFuncSetAttribute(out_gemm,  cudaFuncAttributeMaxDynamicSharedMemorySize, GSMEM_BYTES);
    cudaFuncSetAttribute(attn_mma,  cudaFuncAttributeMaxDynamicSharedMemorySize, ASMEM_BYTES);

    const int n4 = NM * NE / 4;
    round_kernel<<<dim3(512, 1, 3), 256>>>(q, k, v, n4);

    dim3 tt(32, 8);
    transpose_kernel<<<dim3(2, 32, 16), tt>>>(Wq, 0, NE, ND);
    transpose_kernel<<<dim3(2, 32, 16), tt>>>(Wk, 1, NE, ND);
    transpose_kernel<<<dim3(2, 32, 16), tt>>>(Wv, 2, NE, ND);
    transpose_kernel<<<dim3(32, 32, 1), tt>>>(Wo, 3, NE, NE);

    proj_gemm<<<dim3(NM / 128, NE / 256, 3), 256, GSMEM_BYTES>>>(bq, bk, bv);

    attn_mma<<<dim3(NS / 128, NB * NH), 128, ASMEM_BYTES>>>();

    out_gemm<<<dim3(NM / 128, NE / 256), 256, GSMEM_BYTES>>>(bo, out);
}

// round 8
// speedup vs baseline: 1.0752x; 1.0752x over previous
#include <cuda_runtime.h>
#include <math.h>
#include <stdint.h>

#define NB 8
#define NS 1024
#define NE 1024
#define NH 16
#define ND 64
#define NM (NB*NS)

// ---------------- device-global scratch (allocation-free) ------------------
__device__ float g_qh[NB*NH*NS*ND];
__device__ float g_kh[NB*NH*NS*ND];
__device__ float g_vh[NB*NH*NS*ND];
__device__ float g_ctx[NB*NS*NE];
__device__ float g_qr[NM*NE];       // tf32-rounded inputs
__device__ float g_kr[NM*NE];
__device__ float g_vr[NM*NE];
__device__ float g_wqT[NH*ND*NE];   // [n=h*64+e][k], tf32-rounded
__device__ float g_wkT[NH*ND*NE];
__device__ float g_wvT[NH*ND*NE];
__device__ float g_woT[NE*NE];

__device__ __forceinline__ float tf32rna(float x) {
    uint32_t u;
    asm("cvt.rna.tf32.f32 %0, %1;" : "=r"(u) : "f"(x));
    return __uint_as_float(u);
}
__device__ __forceinline__ uint32_t smem_u32(const void* p) {
    uint32_t a;
    asm("{ .reg .u64 t; cvta.to.shared.u64 t, %1; cvt.u32.u64 %0, t; }" : "=r"(a) : "l"(p));
    return a;
}
__device__ __forceinline__ void cpa16(uint32_t dst, const void* src) {
    asm volatile("cp.async.cg.shared.global [%0], [%1], 16;" :: "r"(dst), "l"(src));
}
__device__ __forceinline__ void cpa_commit() {
    asm volatile("cp.async.commit_group;" ::: "memory");
}
template<int N> __device__ __forceinline__ void cpa_wait() {
    asm volatile("cp.async.wait_group %0;" :: "n"(N) : "memory");
}
__device__ __forceinline__ void mma16n8k8(float* d, const uint32_t* a, uint32_t b0, uint32_t b1) {
    asm volatile(
        "mma.sync.aligned.m16n8k8.row.col.f32.tf32.tf32.f32 "
        "{%0,%1,%2,%3}, {%4,%5,%6,%7}, {%8,%9}, {%0,%1,%2,%3};"
        : "+f"(d[0]), "+f"(d[1]), "+f"(d[2]), "+f"(d[3])
        : "r"(a[0]), "r"(a[1]), "r"(a[2]), "r"(a[3]), "r"(b0), "r"(b1));
}

// ---------------- GEMM: 128x128 tile, 3-stage cp.async, 1 sync/chunk -------
#define TSTRIDE 36
#define TILEF  (128*TSTRIDE)             // 4608 floats
#define STAGEF (2*TILEF)                 // 9216 floats = 36864 B
#define GSTAGES 3
#define GSMEM_BYTES (GSTAGES*STAGEF*4)   // 110592 -> 2 CTAs/SM

__device__ __forceinline__ void gemm_body(
    const float* __restrict__ A, const float* __restrict__ BT,
    const float* __restrict__ bias, float* __restrict__ ob, int osel,
    float* sm)
{
    const uint32_t su = smem_u32(sm);
    const int tid  = threadIdx.x;
    const int wid  = tid >> 5;
    const int lane = tid & 31;
    const int g    = lane >> 2;
    const int t    = lane & 3;
    const int m0 = blockIdx.x * 128;
    const int n0 = blockIdx.y * 128;
    const int warp_m = (wid >> 2) * 64;
    const int warp_n = (wid & 3) * 32;

    const int lrow = tid >> 3;        // 0..31
    const int lc4  = tid & 7;         // 0..7

    auto issue = [&](int c, int s) {
        const int k0 = c * 32;
        const uint32_t base = su + s * (STAGEF * 4);
#pragma unroll
        for (int i = 0; i < 4; i++) {
            int row = lrow + i * 32;
            cpa16(base + (row * TSTRIDE + lc4 * 4) * 4,
                  A + (size_t)(m0 + row) * NE + k0 + lc4 * 4);
            cpa16(base + TILEF * 4 + (row * TSTRIDE + lc4 * 4) * 4,
                  BT + (size_t)(n0 + row) * NE + k0 + lc4 * 4);
        }
    };

    issue(0, 0); cpa_commit();
    issue(1, 1); cpa_commit();

    float d[4][4][4];
#pragma unroll
    for (int mi = 0; mi < 4; mi++)
#pragma unroll
        for (int ni = 0; ni < 4; ni++)
#pragma unroll
            for (int j = 0; j < 4; j++) d[mi][ni][j] = 0.f;

    for (int c = 0; c < 32; c++) {
        // stage c ready?  (allow the group issued last iteration to remain in flight)
        if (c < 31) cpa_wait<1>(); else cpa_wait<0>();
        __syncthreads();   // single sync per chunk: all warps done with chunk c-1

        const int st = c % 3;
        const float* As = sm + st * STAGEF + (warp_m + g) * TSTRIDE;
        const float* Bs = sm + st * STAGEF + TILEF + (warp_n + g) * TSTRIDE;
#pragma unroll
        for (int ks = 0; ks < 4; ks++) {
            const int k0 = ks * 8 + t;
            uint32_t a[4][4];
#pragma unroll
            for (int mi = 0; mi < 4; mi++) {
                const float* ap = As + mi * 16 * TSTRIDE + k0;
                a[mi][0] = __float_as_uint(ap[0]);
                a[mi][1] = __float_as_uint(ap[8 * TSTRIDE]);
                a[mi][2] = __float_as_uint(ap[4]);
                a[mi][3] = __float_as_uint(ap[8 * TSTRIDE + 4]);
            }
#pragma unroll
            for (int ni = 0; ni < 4; ni++) {
                const float* bp = Bs + ni * 8 * TSTRIDE + k0;
                uint32_t b0 = __float_as_uint(bp[0]);
                uint32_t b1 = __float_as_uint(bp[4]);
#pragma unroll
                for (int mi = 0; mi < 4; mi++)
                    mma16n8k8(d[mi][ni], a[mi], b0, b1);
            }
        }

        // refill stage (c+2)%3 == (c-1)%3 — safe: sync above proved chunk c-1 consumed
        if (c + 2 < 32) { issue(c + 2, (c + 2) % 3); cpa_commit(); }
    }

    // epilogue: bias + store (proj outputs rounded to tf32 for downstream mma)
#pragma unroll
    for (int mi = 0; mi < 4; mi++) {
#pragma unroll
        for (int ni = 0; ni < 4; ni++) {
            const int r0  = m0 + warp_m + mi * 16 + g;
            const int r1  = r0 + 8;
            const int col = n0 + warp_n + ni * 8 + t * 2;
            const float bx = bias[col], by = bias[col + 1];
            float2 v0, v1;
            v0.x = d[mi][ni][0] + bx; v0.y = d[mi][ni][1] + by;
            v1.x = d[mi][ni][2] + bx; v1.y = d[mi][ni][3] + by;
            if (osel < 3) {
                v0.x = tf32rna(v0.x); v0.y = tf32rna(v0.y);
                v1.x = tf32rna(v1.x); v1.y = tf32rna(v1.y);
                const int h = col >> 6, e = col & 63;
                float* d0 = ob + ((size_t)((r0 >> 10) * NH + h) * NS + (r0 & 1023)) * ND + e;
                float* d1 = ob + ((size_t)((r1 >> 10) * NH + h) * NS + (r1 & 1023)) * ND + e;
                *(float2*)d0 = v0;
                *(float2*)d1 = v1;
            } else {
                *(float2*)(ob + (size_t)r0 * NE + col) = v0;
                *(float2*)(ob + (size_t)r1 * NE + col) = v1;
            }
        }
    }
}

// fused Q/K/V projection GEMMs: blockIdx.z = 0/1/2
__global__ __launch_bounds__(256, 2) void proj_gemm(
    const float* __restrict__ bq, const float* __restrict__ bk,
    const float* __restrict__ bv)
{
    extern __shared__ float sm[];
    const int z = blockIdx.z;
    const float* A  = (z == 0) ? g_qr  : (z == 1) ? g_kr  : g_vr;
    const float* BT = (z == 0) ? g_wqT : (z == 1) ? g_wkT : g_wvT;
    const float* bias = (z == 0) ? bq : (z == 1) ? bk : bv;
    float* ob = (z == 0) ? g_qh : (z == 1) ? g_kh : g_vh;
    gemm_body(A, BT, bias, ob, z, sm);
}

__global__ __launch_bounds__(256, 2) void out_gemm(
    const float* __restrict__ bo, float* __restrict__ out)
{
    extern __shared__ float sm[];
    gemm_body(g_ctx, g_woT, bo, out, 3, sm);
}

// ---------------- attention: tf32 mma flash, 1 sync per kv-tile ------------
#define KSTR 68
#define VSTR 72
#define QPF  (128*KSTR)                 // 8704 floats (Q, reused as P)
#define KVF  (64*KSTR + 64*VSTR)        // 8960 floats per stage
#define ASTAGES 2
#define ASMEM_BYTES ((QPF + ASTAGES*KVF)*4)  // 106496 -> 2 CTAs/SM

__global__ __launch_bounds__(256, 2) void attn_mma()
{
    extern __shared__ float smf[];
    const uint32_t su = smem_u32(smf);
    const int tid = threadIdx.x, wid = tid >> 5, lane = tid & 31;
    const int g = lane >> 2, t = lane & 3;
    const int bh = blockIdx.y;
    const int s0 = blockIdx.x * 128;
    const int w16 = wid * 16;
    const float* Qp = g_qh + (size_t)bh * NS * ND;
    const float* Kp = g_kh + (size_t)bh * NS * ND;
    const float* Vp = g_vh + (size_t)bh * NS * ND;

    const int lkv = tid >> 4;          // 0..15
    const int lc4 = tid & 15;          // 0..15

    auto issue_kv = [&](int kt, int st) {
        const uint32_t kB = su + QPF * 4 + st * (KVF * 4);
        const uint32_t vB = kB + 64 * KSTR * 4;
        const float* Ks = Kp + (size_t)kt * 64 * ND;
        const float* Vs = Vp + (size_t)kt * 64 * ND;
#pragma unroll
        for (int i = 0; i < 4; i++) {
            int kv = lkv + i * 16;
            cpa16(kB + (kv * KSTR + lc4 * 4) * 4, Ks + (size_t)kv * ND + lc4 * 4);
            cpa16(vB + (kv * VSTR + lc4 * 4) * 4, Vs + (size_t)kv * ND + lc4 * 4);
        }
    };

    issue_kv(0, 0); cpa_commit();

    // Q tile -> smem (stride 68)
#pragma unroll
    for (int i = 0; i < 8; i++) {
        int idx = tid + i * 256;
        int row = idx >> 4, c4 = idx & 15;
        *(float4*)(smf + row * KSTR + c4 * 4) =
            *(const float4*)(Qp + (size_t)(s0 + row) * ND + c4 * 4);
    }
    __syncthreads();

    // persistent Q fragments
    uint32_t qf[8][4];
    {
        const float* qp = smf + (w16 + g) * KSTR;
#pragma unroll
        for (int ks = 0; ks < 8; ks++) {
            qf[ks][0] = __float_as_uint(qp[ks * 8 + t]);
            qf[ks][1] = __float_as_uint(qp[8 * KSTR + ks * 8 + t]);
            qf[ks][2] = __float_as_uint(qp[ks * 8 + t + 4]);
            qf[ks][3] = __float_as_uint(qp[8 * KSTR + ks * 8 + t + 4]);
        }
    }

    float o[8][4];
#pragma unroll
    for (int ni = 0; ni < 8; ni++)
#pragma unroll
        for (int j = 0; j < 4; j++) o[ni][j] = 0.f;
    float mA = -1e30f, mB = -1e30f, lA = 0.f, lB = 0.f;
    const float scale = 0.125f;

    for (int kt = 0; kt < 16; kt++) {
        cpa_wait<0>();        // stage kt&1 fully landed (only group in flight)
        __syncthreads();      // single sync: all warps done with kt-1
        // refill the other stage == (kt-1)&1 — safe per the sync above
        if (kt + 1 < 16) { issue_kv(kt + 1, (kt + 1) & 1); cpa_commit(); }

        const int st = kt & 1;
        const float* sK = smf + QPF + st * KVF;
        const float* sV = sK + 64 * KSTR;

        // S = Q @ K^T
        float s[8][4];
#pragma unroll
        for (int ni = 0; ni < 8; ni++)
#pragma unroll
            for (int j = 0; j < 4; j++) s[ni][j] = 0.f;
#pragma unroll
        for (int ks = 0; ks < 8; ks++) {
            const float* kp = sK + ks * 8 + t;
#pragma unroll
            for (int ni = 0; ni < 8; ni++) {
                uint32_t b0 = __float_as_uint(kp[(ni * 8 + g) * KSTR]);
                uint32_t b1 = __float_as_uint(kp[(ni * 8 + g) * KSTR + 4]);
                mma16n8k8(s[ni], qf[ks], b0, b1);
            }
        }

        // online softmax (rows g and g+8)
        float mxA = -1e30f, mxB = -1e30f;
#pragma unroll
        for (int ni = 0; ni < 8; ni++) {
            mxA = fmaxf(mxA, fmaxf(s[ni][0], s[ni][1]));
            mxB = fmaxf(mxB, fmaxf(s[ni][2], s[ni][3]));
        }
        mxA = fmaxf(mxA, __shfl_xor_sync(0xffffffffu, mxA, 1));
        mxA = fmaxf(mxA, __shfl_xor_sync(0xffffffffu, mxA, 2));
        mxB = fmaxf(mxB, __shfl_xor_sync(0xffffffffu, mxB, 1));
        mxB = fmaxf(mxB, __shfl_xor_sync(0xffffffffu, mxB, 2));
        float mAn = fmaxf(mA, mxA * scale);
        float mBn = fmaxf(mB, mxB * scale);
        float aA = __expf(mA - mAn), aB = __expf(mB - mBn);
        float sumA = 0.f, sumB = 0.f;
#pragma unroll
        for (int ni = 0; ni < 8; ni++) {
            s[ni][0] = __expf(s[ni][0] * scale - mAn);
            s[ni][1] = __expf(s[ni][1] * scale - mAn);
            s[ni][2] = __expf(s[ni][2] * scale - mBn);
            s[ni][3] = __expf(s[ni][3] * scale - mBn);
            sumA += s[ni][0] + s[ni][1];
            sumB += s[ni][2] + s[ni][3];
        }
        sumA += __shfl_xor_sync(0xffffffffu, sumA, 1);
        sumA += __shfl_xor_sync(0xffffffffu, sumA, 2);
        sumB += __shfl_xor_sync(0xffffffffu, sumB, 1);
        sumB += __shfl_xor_sync(0xffffffffu, sumB, 2);
        lA = lA * aA + sumA; lB = lB * aB + sumB;
        mA = mAn; mB = mBn;
#pragma unroll
        for (int ni = 0; ni < 8; ni++) {
            o[ni][0] *= aA; o[ni][1] *= aA;
            o[ni][2] *= aB; o[ni][3] *= aB;
        }

        // publish P (tf32-rounded) into QP buffer (own warp's rows only)
        float* pr = smf + (w16 + g) * KSTR;
        __syncwarp();
#pragma unroll
        for (int ni = 0; ni < 8; ni++) {
            float2 v0; v0.x = tf32rna(s[ni][0]); v0.y = tf32rna(s[ni][1]);
            float2 v1; v1.x = tf32rna(s[ni][2]); v1.y = tf32rna(s[ni][3]);
            *(float2*)(pr + ni * 8 + 2 * t) = v0;
            *(float2*)(pr + 8 * KSTR + ni * 8 + 2 * t) = v1;
        }
        __syncwarp();

        // O += P @ V
#pragma unroll
        for (int ks = 0; ks < 8; ks++) {
            uint32_t a[4];
            a[0] = __float_as_uint(pr[ks * 8 + t]);
            a[1] = __float_as_uint(pr[8 * KSTR + ks * 8 + t]);
            a[2] = __float_as_uint(pr[ks * 8 + t + 4]);
            a[3] = __float_as_uint(pr[8 * KSTR + ks * 8 + t + 4]);
            const float* vp = sV + (ks * 8 + t) * VSTR;
#pragma unroll
            for (int ni = 0; ni < 8; ni++) {
                uint32_t b0 = __float_as_uint(vp[ni * 8 + g]);
                uint32_t b1 = __float_as_uint(vp[4 * VSTR + ni * 8 + g]);
                mma16n8k8(o[ni], a, b0, b1);
            }
        }
    }

    // epilogue: normalize, round, write ctx
    const float iA = 1.f / lA, iB = 1.f / lB;
    const int b = bh >> 4, h = bh & 15;
    const int rA = s0 + w16 + g, rB = rA + 8;
    float* dA = g_ctx + (size_t)(b * NS + rA) * NE + h * 64;
    float* dB = g_ctx + (size_t)(b * NS + rB) * NE + h * 64;
#pragma unroll
    for (int ni = 0; ni < 8; ni++) {
        float2 vA, vB2;
        vA.x  = tf32rna(o[ni][0] * iA); vA.y  = tf32rna(o[ni][1] * iA);
        vB2.x = tf32rna(o[ni][2] * iB); vB2.y = tf32rna(o[ni][3] * iB);
        *(float2*)(dA + ni * 8 + 2 * t) = vA;
        *(float2*)(dB + ni * 8 + 2 * t) = vB2;
    }
}

// ---------------- small prep kernels ----------------------------------------
__global__ void round_kernel(const float* __restrict__ q, const float* __restrict__ k,
                             const float* __restrict__ v, int n4)
{
    const int z = blockIdx.z;
    const float* in = (z == 0) ? q : (z == 1) ? k : v;
    float* out = (z == 0) ? g_qr : (z == 1) ? g_kr : g_vr;
    int i = blockIdx.x * blockDim.x + threadIdx.x;
    for (; i < n4; i += gridDim.x * blockDim.x) {
        float4 w = ((const float4*)in)[i];
        w.x = tf32rna(w.x); w.y = tf32rna(w.y);
        w.z = tf32rna(w.z); w.w = tf32rna(w.w);
        ((float4*)out)[i] = w;
    }
}

// Fused transpose of Wq/Wk/Wv (per-head 1024x64 slices) and Wo (1024x1024).
// grid (32, 32, 4): z=0..2 -> Wq/Wk/Wv (x encodes head*2+colblock), z=3 -> Wo.
__global__ void transpose_all(const float* __restrict__ Wq, const float* __restrict__ Wk,
                              const float* __restrict__ Wv, const float* __restrict__ Wo)
{
    __shared__ float tbuf[32][33];
    const int z = blockIdx.z;
    const float* I;
    float* O;
    int R, C, c0, r0;
    if (z < 3) {
        const float* W = (z == 0) ? Wq : (z == 1) ? Wk : Wv;
        float* out = (z == 0) ? g_wqT : (z == 1) ? g_wkT : g_wvT;
        const int h = blockIdx.x >> 1;
        R = NE; C = ND;
        I = W   + (size_t)h * R * C;
        O = out + (size_t)h * R * C;
        c0 = (blockIdx.x & 1) * 32;
        r0 = blockIdx.y * 32;
    } else {
        R = NE; C = NE;
        I = Wo; O = g_woT;
        c0 = blockIdx.x * 32;
        r0 = blockIdx.y * 32;
    }
#pragma unroll
    for (int j = threadIdx.y; j < 32; j += 8)
        tbuf[j][threadIdx.x] = I[(size_t)(r0 + j) * C + c0 + threadIdx.x];
    __syncthreads();
#pragma unroll
    for (int j = threadIdx.y; j < 32; j += 8)
        O[(size_t)(c0 + j) * R + r0 + threadIdx.x] = tf32rna(tbuf[threadIdx.x][j]);
}

// ---------------------------------------------------------------------------
extern "C" void kernel_launch(void* const* d_in, const int* in_sizes, int n_in,
                              void* d_out, int out_size)
{
    const float* q  = (const float*)d_in[0];
    const float* k  = (const float*)d_in[1];
    const float* v  = (const float*)d_in[2];
    const float* Wq = (const float*)d_in[3];
    const float* bq = (const float*)d_in[4];
    const float* Wk = (const float*)d_in[5];
    const float* bk = (const float*)d_in[6];
    const float* Wv = (const float*)d_in[7];
    const float* bv = (const float*)d_in[8];
    const float* Wo = (const float*)d_in[9];
    const float* bo = (const float*)d_in[10];
    float* out = (float*)d_out;

    cudaFuncSetAttribute(proj_gemm, cudaFuncAttributeMaxDynamicSharedMemorySize, GSMEM_BYTES);
    cudaFuncSetAttribute(out_gemm,  cudaFuncAttributeMaxDynamicSharedMemorySize, GSMEM_BYTES);
    cudaFuncSetAttribute(attn_mma,  cudaFuncAttributeMaxDynamicSharedMemorySize, ASMEM_BYTES);

    const int n4 = NM * NE / 4;
    round_kernel<<<dim3(512, 1, 3), 256>>>(q, k, v, n4);

    transpose_all<<<dim3(32, 32, 4), dim3(32, 8)>>>(Wq, Wk, Wv, Wo);

    proj_gemm<<<dim3(NM / 128, NE / 128, 3), 256, GSMEM_BYTES>>>(bq, bk, bv);

    attn_mma<<<dim3(NS / 128, NB * NH), 256, ASMEM_BYTES>>>();

    out_gemm<<<dim3(NM / 128, NE / 128), 256, GSMEM_BYTES>>>(bo, out);
}